// round 1
// baseline (speedup 1.0000x reference)
#include <cuda_runtime.h>
#include <cuda_bf16.h>

// Problem constants
#define Bn    8
#define CIN   128
#define COUT  128
#define Hn    64
#define Wn    64
#define KK    9
#define HW    (Hn * Wn)          // 4096
#define EPSV  1e-4f

#define TILE_P 32                // pixels per block (one half-row)
#define NTHREADS 128

// Normalized weights, layout [k][c][o] (o contiguous for coalesced GEMM loads)
__device__ float g_wn[KK * CIN * COUT];

// ---------------------------------------------------------------------------
// Kernel 1: weight normalization
// wn[o][c][k] = w[o][c][k] / (sqrt(sum_c w^2 + CIN*eps) * 3)
// stored as g_wn[k*CIN*COUT + c*COUT + o]
// ---------------------------------------------------------------------------
__global__ void normw_kernel(const float* __restrict__ w) {
    int k = blockIdx.x;      // 0..8
    int o = threadIdx.x;     // 0..127
    float s = 0.f;
    #pragma unroll 8
    for (int c = 0; c < CIN; c++) {
        float v = w[(o * CIN + c) * KK + k];
        s += v * v;
    }
    float inv = 1.0f / (sqrtf(s + CIN * EPSV) * 3.0f);
    #pragma unroll 8
    for (int c = 0; c < CIN; c++) {
        g_wn[(k * CIN + c) * COUT + o] = w[(o * CIN + c) * KK + k] * inv;
    }
}

// ---------------------------------------------------------------------------
// Kernel 2: deformable conv main
// Each block: 32 contiguous pixels (same b, same output row) x 128 couts.
// Loop over k (9) and c-chunks (4 x 32):
//   - gather cols_s[32c][32px] via bilinear sampling (corner params computed
//     once per (px,k), reused for 32 channels)
//   - load wn_s[32c][128o] coalesced
//   - register-blocked FFMA: each thread 8 couts x 4 pixels
// ---------------------------------------------------------------------------
__global__ __launch_bounds__(NTHREADS, 4)
void deform_main_kernel(const float* __restrict__ x,
                        const float* __restrict__ offset,
                        float* __restrict__ out) {
    const int p0  = blockIdx.x * TILE_P;      // first pixel of tile
    const int b   = p0 / HW;
    const int rem = p0 - b * HW;
    const int ho  = rem / Wn;
    const int wo0 = rem - ho * Wn;            // 0 or 32

    const int t   = threadIdx.x;              // 0..127
    // GEMM thread mapping: 16 cout-groups x 8 pixel-groups
    const int cg  = t >> 3;                   // 0..15 -> couts cg*8 .. cg*8+7
    const int pg  = t & 7;                    // 0..7  -> pixels pg*4 .. pg*4+3
    // gather thread mapping: 32 pixels x 4 c-subgroups of 8
    const int gpx = t & 31;                   // pixel this thread gathers for
    const int gc0 = (t >> 5) * 8;             // c-subrange base within chunk

    __shared__ float cols_s[32][TILE_P];      // [c][px]
    __shared__ float wn_s[32][COUT];          // [c][o]

    float acc[8][4];
    #pragma unroll
    for (int i = 0; i < 8; i++)
        #pragma unroll
        for (int j = 0; j < 4; j++) acc[i][j] = 0.f;

    const float* xb = x + (size_t)b * CIN * HW;

    for (int k = 0; k < KK; k++) {
        const int ky = k / 3, kx = k - ky * 3;

        // ---- per-(px,k) bilinear parameters (this thread's gather pixel) ----
        const int wo = wo0 + gpx;
        const float offy = offset[(((b * (2 * KK)) + 2 * k    ) * Hn + ho) * Wn + wo];
        const float offx = offset[(((b * (2 * KK)) + 2 * k + 1) * Hn + ho) * Wn + wo];
        const float py  = (float)(ho - 1 + ky) + offy;
        const float pxf = (float)(wo - 1 + kx) + offx;
        const float y0f = floorf(py), x0f = floorf(pxf);
        const float ly = py - y0f, lx = pxf - x0f;
        const int y0 = (int)y0f, x0 = (int)x0f;
        const int y1 = y0 + 1,  x1 = x0 + 1;

        float w00 = (1.f - ly) * (1.f - lx);
        float w01 = (1.f - ly) * lx;
        float w10 = ly * (1.f - lx);
        float w11 = ly * lx;
        const bool vy0 = (y0 >= 0) & (y0 < Hn);
        const bool vy1 = (y1 >= 0) & (y1 < Hn);
        const bool vx0 = (x0 >= 0) & (x0 < Wn);
        const bool vx1 = (x1 >= 0) & (x1 < Wn);
        if (!(vy0 & vx0)) w00 = 0.f;
        if (!(vy0 & vx1)) w01 = 0.f;
        if (!(vy1 & vx0)) w10 = 0.f;
        if (!(vy1 & vx1)) w11 = 0.f;
        const int yc0 = min(max(y0, 0), Hn - 1);
        const int yc1 = min(max(y1, 0), Hn - 1);
        const int xc0 = min(max(x0, 0), Wn - 1);
        const int xc1 = min(max(x1, 0), Wn - 1);
        const int i00 = yc0 * Wn + xc0;
        const int i01 = yc0 * Wn + xc1;
        const int i10 = yc1 * Wn + xc0;
        const int i11 = yc1 * Wn + xc1;

        const float* wn_k = g_wn + k * CIN * COUT;

        for (int cc = 0; cc < CIN / 32; cc++) {
            const int cbase = cc * 32;
            __syncthreads();   // previous chunk's FMAs done before overwrite

            // gather: this thread fills cols_s[gc0..gc0+7][gpx]
            #pragma unroll
            for (int j = 0; j < 8; j++) {
                const float* xc = xb + (size_t)(cbase + gc0 + j) * HW;
                float v = w00 * __ldg(xc + i00) + w01 * __ldg(xc + i01)
                        + w10 * __ldg(xc + i10) + w11 * __ldg(xc + i11);
                cols_s[gc0 + j][gpx] = v;
            }
            // wn chunk: 32 x 128 floats, coalesced
            #pragma unroll
            for (int i = 0; i < 32; i++) {
                wn_s[i][t] = wn_k[(cbase + i) * COUT + t];
            }
            __syncthreads();

            // FMA microkernel: 8 couts x 4 pixels x 32 c
            #pragma unroll
            for (int c = 0; c < 32; c++) {
                const float4 a0 = *reinterpret_cast<const float4*>(&wn_s[c][cg * 8]);
                const float4 a1 = *reinterpret_cast<const float4*>(&wn_s[c][cg * 8 + 4]);
                const float4 bv = *reinterpret_cast<const float4*>(&cols_s[c][pg * 4]);
                const float av[8] = {a0.x, a0.y, a0.z, a0.w, a1.x, a1.y, a1.z, a1.w};
                const float bvv[4] = {bv.x, bv.y, bv.z, bv.w};
                #pragma unroll
                for (int i = 0; i < 8; i++)
                    #pragma unroll
                    for (int j = 0; j < 4; j++)
                        acc[i][j] = fmaf(av[i], bvv[j], acc[i][j]);
            }
        }
    }

    // ---- epilogue: out[b][o][ho][wo] ----
    const int pix_base = ho * Wn + wo0 + pg * 4;
    #pragma unroll
    for (int i = 0; i < 8; i++) {
        const int o = cg * 8 + i;
        float4 v = make_float4(acc[i][0], acc[i][1], acc[i][2], acc[i][3]);
        *reinterpret_cast<float4*>(out + ((size_t)b * COUT + o) * HW + pix_base) = v;
    }
}

// ---------------------------------------------------------------------------
extern "C" void kernel_launch(void* const* d_in, const int* in_sizes, int n_in,
                              void* d_out, int out_size) {
    const float* x      = (const float*)d_in[0];   // (8,128,64,64)
    const float* offset = (const float*)d_in[1];   // (8,18,64,64)
    const float* weight = (const float*)d_in[2];   // (128,128,3,3)
    float* out = (float*)d_out;                    // (8,128,64,64)

    normw_kernel<<<KK, COUT>>>(weight);
    const int nblocks = (Bn * HW) / TILE_P;        // 1024
    deform_main_kernel<<<nblocks, NTHREADS>>>(x, offset, out);
}

// round 2
// speedup vs baseline: 1.0538x; 1.0538x over previous
#include <cuda_runtime.h>
#include <cuda_bf16.h>

// Problem constants
#define Bn    8
#define CIN   128
#define COUT  128
#define Hn    64
#define Wn    64
#define KK    9
#define HW    (Hn * Wn)          // 4096
#define EPSV  1e-4f

#define TILE_P 32                // pixels per block (one half-row)
#define NTHREADS 128

// Normalized weights, layout [k][c][o] (o contiguous for coalesced GEMM loads)
__device__ float g_wn[KK * CIN * COUT];

// ---------------------------------------------------------------------------
// Kernel 1: weight normalization
// wn[o][c][k] = w[o][c][k] / (sqrt(sum_c w^2 + CIN*eps) * 3)
// stored as g_wn[k*CIN*COUT + c*COUT + o]
// ---------------------------------------------------------------------------
__global__ void normw_kernel(const float* __restrict__ w) {
    int k = blockIdx.x;      // 0..8
    int o = threadIdx.x;     // 0..127
    float s = 0.f;
    #pragma unroll 8
    for (int c = 0; c < CIN; c++) {
        float v = w[(o * CIN + c) * KK + k];
        s += v * v;
    }
    float inv = 1.0f / (sqrtf(s + CIN * EPSV) * 3.0f);
    #pragma unroll 8
    for (int c = 0; c < CIN; c++) {
        g_wn[(k * CIN + c) * COUT + o] = w[(o * CIN + c) * KK + k] * inv;
    }
}

// ---------------------------------------------------------------------------
// Kernel 2: deformable conv main
// Each block: 32 contiguous pixels (same b, same output row) x 128 couts.
// Loop over k (9) and c-chunks (4 x 32):
//   - gather cols_s[32c][32px] via bilinear sampling (corner params computed
//     once per (px,k), reused for 32 channels)
//   - load wn_s[32c][128o] coalesced
//   - register-blocked FFMA: each thread 8 couts x 4 pixels
// ---------------------------------------------------------------------------
__global__ __launch_bounds__(NTHREADS, 4)
void deform_main_kernel(const float* __restrict__ x,
                        const float* __restrict__ offset,
                        float* __restrict__ out) {
    const int p0  = blockIdx.x * TILE_P;      // first pixel of tile
    const int b   = p0 / HW;
    const int rem = p0 - b * HW;
    const int ho  = rem / Wn;
    const int wo0 = rem - ho * Wn;            // 0 or 32

    const int t   = threadIdx.x;              // 0..127
    // GEMM thread mapping: 16 cout-groups x 8 pixel-groups
    const int cg  = t >> 3;                   // 0..15 -> couts cg*8 .. cg*8+7
    const int pg  = t & 7;                    // 0..7  -> pixels pg*4 .. pg*4+3
    // gather thread mapping: 32 pixels x 4 c-subgroups of 8
    const int gpx = t & 31;                   // pixel this thread gathers for
    const int gc0 = (t >> 5) * 8;             // c-subrange base within chunk

    __shared__ float cols_s[32][TILE_P];      // [c][px]
    __shared__ float wn_s[32][COUT];          // [c][o]

    float acc[8][4];
    #pragma unroll
    for (int i = 0; i < 8; i++)
        #pragma unroll
        for (int j = 0; j < 4; j++) acc[i][j] = 0.f;

    const float* xb = x + (size_t)b * CIN * HW;

    for (int k = 0; k < KK; k++) {
        const int ky = k / 3, kx = k - ky * 3;

        // ---- per-(px,k) bilinear parameters (this thread's gather pixel) ----
        const int wo = wo0 + gpx;
        const float offy = offset[(((b * (2 * KK)) + 2 * k    ) * Hn + ho) * Wn + wo];
        const float offx = offset[(((b * (2 * KK)) + 2 * k + 1) * Hn + ho) * Wn + wo];
        const float py  = (float)(ho - 1 + ky) + offy;
        const float pxf = (float)(wo - 1 + kx) + offx;
        const float y0f = floorf(py), x0f = floorf(pxf);
        const float ly = py - y0f, lx = pxf - x0f;
        const int y0 = (int)y0f, x0 = (int)x0f;
        const int y1 = y0 + 1,  x1 = x0 + 1;

        float w00 = (1.f - ly) * (1.f - lx);
        float w01 = (1.f - ly) * lx;
        float w10 = ly * (1.f - lx);
        float w11 = ly * lx;
        const bool vy0 = (y0 >= 0) & (y0 < Hn);
        const bool vy1 = (y1 >= 0) & (y1 < Hn);
        const bool vx0 = (x0 >= 0) & (x0 < Wn);
        const bool vx1 = (x1 >= 0) & (x1 < Wn);
        if (!(vy0 & vx0)) w00 = 0.f;
        if (!(vy0 & vx1)) w01 = 0.f;
        if (!(vy1 & vx0)) w10 = 0.f;
        if (!(vy1 & vx1)) w11 = 0.f;
        const int yc0 = min(max(y0, 0), Hn - 1);
        const int yc1 = min(max(y1, 0), Hn - 1);
        const int xc0 = min(max(x0, 0), Wn - 1);
        const int xc1 = min(max(x1, 0), Wn - 1);
        const int i00 = yc0 * Wn + xc0;
        const int i01 = yc0 * Wn + xc1;
        const int i10 = yc1 * Wn + xc0;
        const int i11 = yc1 * Wn + xc1;

        const float* wn_k = g_wn + k * CIN * COUT;

        for (int cc = 0; cc < CIN / 32; cc++) {
            const int cbase = cc * 32;
            __syncthreads();   // previous chunk's FMAs done before overwrite

            // gather: this thread fills cols_s[gc0..gc0+7][gpx]
            #pragma unroll
            for (int j = 0; j < 8; j++) {
                const float* xc = xb + (size_t)(cbase + gc0 + j) * HW;
                float v = w00 * __ldg(xc + i00) + w01 * __ldg(xc + i01)
                        + w10 * __ldg(xc + i10) + w11 * __ldg(xc + i11);
                cols_s[gc0 + j][gpx] = v;
            }
            // wn chunk: 32 x 128 floats, coalesced
            #pragma unroll
            for (int i = 0; i < 32; i++) {
                wn_s[i][t] = wn_k[(cbase + i) * COUT + t];
            }
            __syncthreads();

            // FMA microkernel: 8 couts x 4 pixels x 32 c
            #pragma unroll
            for (int c = 0; c < 32; c++) {
                const float4 a0 = *reinterpret_cast<const float4*>(&wn_s[c][cg * 8]);
                const float4 a1 = *reinterpret_cast<const float4*>(&wn_s[c][cg * 8 + 4]);
                const float4 bv = *reinterpret_cast<const float4*>(&cols_s[c][pg * 4]);
                const float av[8] = {a0.x, a0.y, a0.z, a0.w, a1.x, a1.y, a1.z, a1.w};
                const float bvv[4] = {bv.x, bv.y, bv.z, bv.w};
                #pragma unroll
                for (int i = 0; i < 8; i++)
                    #pragma unroll
                    for (int j = 0; j < 4; j++)
                        acc[i][j] = fmaf(av[i], bvv[j], acc[i][j]);
            }
        }
    }

    // ---- epilogue: out[b][o][ho][wo] ----
    const int pix_base = ho * Wn + wo0 + pg * 4;
    #pragma unroll
    for (int i = 0; i < 8; i++) {
        const int o = cg * 8 + i;
        float4 v = make_float4(acc[i][0], acc[i][1], acc[i][2], acc[i][3]);
        *reinterpret_cast<float4*>(out + ((size_t)b * COUT + o) * HW + pix_base) = v;
    }
}

// ---------------------------------------------------------------------------
extern "C" void kernel_launch(void* const* d_in, const int* in_sizes, int n_in,
                              void* d_out, int out_size) {
    const float* x      = (const float*)d_in[0];   // (8,128,64,64)
    const float* offset = (const float*)d_in[1];   // (8,18,64,64)
    const float* weight = (const float*)d_in[2];   // (128,128,3,3)
    float* out = (float*)d_out;                    // (8,128,64,64)

    normw_kernel<<<KK, COUT>>>(weight);
    const int nblocks = (Bn * HW) / TILE_P;        // 1024
    deform_main_kernel<<<nblocks, NTHREADS>>>(x, offset, out);
}

// round 4
// speedup vs baseline: 1.6766x; 1.5910x over previous
#include <cuda_runtime.h>
#include <cstdint>

#define Bn 8
#define Hn 64
#define Wn 64
#define HW 4096
#define KK 9
#define EPSV 1e-4f
#define SA 132              // wn_s row stride (floats): (4q+g)%32 unique
#define SB 36               // cols_s row stride (floats): (4g+q)%32 unique

__device__ float g_xt[Bn * HW * 128];       // x transposed [b][hw][c]
__device__ float g_wnt[KK * 128 * 128];     // normalized wn [k][c][o], tf32-rounded

__device__ __forceinline__ float to_tf32(float x) {
    float r; asm("cvt.rna.tf32.f32 %0, %1;" : "=f"(r) : "f"(x)); return r;
}

__device__ __forceinline__ void mma_tf32(float* d, const uint32_t* a, const uint32_t* b) {
    asm volatile(
        "mma.sync.aligned.m16n8k8.row.col.f32.tf32.tf32.f32 "
        "{%0,%1,%2,%3}, {%4,%5,%6,%7}, {%8,%9}, {%0,%1,%2,%3};"
        : "+f"(d[0]), "+f"(d[1]), "+f"(d[2]), "+f"(d[3])
        : "r"(a[0]), "r"(a[1]), "r"(a[2]), "r"(a[3]), "r"(b[0]), "r"(b[1]));
}

// ---- kernel 1: transpose x[b][c][hw] -> g_xt[b][hw][c] ----
__global__ void transpose_kernel(const float* __restrict__ x) {
    __shared__ float s[32][33];
    int id = blockIdx.x;
    int b = id >> 9, rest = id & 511;
    int c0 = (rest >> 7) * 32, hw0 = (rest & 127) * 32;
    int tx = threadIdx.x & 31, ty = threadIdx.x >> 5;
    #pragma unroll
    for (int p = 0; p < 4; p++)
        s[ty + p * 8][tx] = x[(size_t)(b * 128 + c0 + ty + p * 8) * HW + hw0 + tx];
    __syncthreads();
    #pragma unroll
    for (int p = 0; p < 4; p++)
        g_xt[(size_t)(b * HW + hw0 + ty + p * 8) * 128 + c0 + tx] = s[tx][ty + p * 8];
}

// ---- kernel 2: normalize weights -> g_wnt[k][c][o], tf32-rounded ----
__global__ void normw_kernel(const float* __restrict__ w) {
    int k = blockIdx.x, o = threadIdx.x;
    float s = 0.f;
    #pragma unroll 8
    for (int c = 0; c < 128; c++) { float v = w[(o * 128 + c) * KK + k]; s += v * v; }
    float inv = 1.0f / (sqrtf(s + 128.0f * EPSV) * 3.0f);
    #pragma unroll 8
    for (int c = 0; c < 128; c++)
        g_wnt[(k * 128 + c) * 128 + o] = to_tf32(w[(o * 128 + c) * KK + k] * inv);
}

// ---- kernel 3: main — im2col gather + tf32 mma.sync GEMM ----
// block = (b, row-pair): D[128co][128px], 8 warps each 32co x 64px
__global__ __launch_bounds__(256, 2)
void deform_main_kernel(const float* __restrict__ offset, float* __restrict__ out) {
    __shared__ float wn_s[32 * SA];     // [c_local][o]
    __shared__ float cols_s[128 * SB];  // [px][c_local]

    const int t = threadIdx.x;
    const int b = blockIdx.x >> 5;
    const int ho0 = (blockIdx.x & 31) * 2;

    // gather mapping: thread -> (pixel, channel-half)
    const int gpx = t >> 1, h = t & 1;
    const int gho = ho0 + (gpx >> 6), gwo = gpx & 63;
    // mma mapping
    const int w = t >> 5, lane = t & 31;
    const int m0 = (w & 3) * 32, n0 = (w >> 2) * 64;
    const int g = lane >> 2, q = lane & 3;

    float acc[2][8][4];
    #pragma unroll
    for (int mt = 0; mt < 2; mt++)
        #pragma unroll
        for (int nt = 0; nt < 8; nt++)
            #pragma unroll
            for (int r = 0; r < 4; r++) acc[mt][nt][r] = 0.f;

    const float* xb = g_xt + (size_t)b * HW * 128;

    for (int k = 0; k < KK; k++) {
        const int ky = k / 3, kx = k - ky * 3;
        const float offy = offset[(((b * 18) + 2 * k    ) * Hn + gho) * Wn + gwo];
        const float offx = offset[(((b * 18) + 2 * k + 1) * Hn + gho) * Wn + gwo];
        const float py  = (float)(gho - 1 + ky) + offy;
        const float pxf = (float)(gwo - 1 + kx) + offx;
        const float y0f = floorf(py), x0f = floorf(pxf);
        const float ly = py - y0f, lx = pxf - x0f;
        const int y0 = (int)y0f, x0 = (int)x0f, y1 = y0 + 1, x1 = x0 + 1;
        float w00 = (1.f - ly) * (1.f - lx), w01 = (1.f - ly) * lx;
        float w10 = ly * (1.f - lx),        w11 = ly * lx;
        if (!((y0 >= 0) & (y0 < Hn) & (x0 >= 0) & (x0 < Wn))) w00 = 0.f;
        if (!((y0 >= 0) & (y0 < Hn) & (x1 >= 0) & (x1 < Wn))) w01 = 0.f;
        if (!((y1 >= 0) & (y1 < Hn) & (x0 >= 0) & (x0 < Wn))) w10 = 0.f;
        if (!((y1 >= 0) & (y1 < Hn) & (x1 >= 0) & (x1 < Wn))) w11 = 0.f;
        const int yc0 = min(max(y0, 0), Hn - 1), yc1 = min(max(y1, 0), Hn - 1);
        const int xc0 = min(max(x0, 0), Wn - 1), xc1 = min(max(x1, 0), Wn - 1);
        const float* p00 = xb + (size_t)(yc0 * Wn + xc0) * 128;
        const float* p01 = xb + (size_t)(yc0 * Wn + xc1) * 128;
        const float* p10 = xb + (size_t)(yc1 * Wn + xc0) * 128;
        const float* p11 = xb + (size_t)(yc1 * Wn + xc1) * 128;

        for (int cc = 0; cc < 4; cc++) {
            __syncthreads();    // previous chunk's MMAs done

            // stage wn chunk [32c x 128o] -> wn_s (coalesced LDG.128, STS.128)
            {
                const float4* src = (const float4*)(g_wnt + (size_t)(k * 4 + cc) * 4096);
                #pragma unroll
                for (int j = 0; j < 4; j++) {
                    int f = j * 256 + t;
                    float4 v = src[f];
                    int c = f >> 5, o4 = (f & 31) * 4;
                    *(float4*)&wn_s[c * SA + o4] = v;
                }
            }
            // gather cols chunk: this thread fills cols_s[gpx][h*16 .. h*16+15]
            {
                #pragma unroll
                for (int j = 0; j < 4; j++) {
                    const int co = cc * 32 + h * 16 + j * 4;  // global channel
                    float4 a = *(const float4*)(p00 + co);
                    float4 bb = *(const float4*)(p01 + co);
                    float4 c = *(const float4*)(p10 + co);
                    float4 d = *(const float4*)(p11 + co);
                    float4 v;
                    v.x = to_tf32(w00 * a.x + w01 * bb.x + w10 * c.x + w11 * d.x);
                    v.y = to_tf32(w00 * a.y + w01 * bb.y + w10 * c.y + w11 * d.y);
                    v.z = to_tf32(w00 * a.z + w01 * bb.z + w10 * c.z + w11 * d.z);
                    v.w = to_tf32(w00 * a.w + w01 * bb.w + w10 * c.w + w11 * d.w);
                    *(float4*)&cols_s[gpx * SB + h * 16 + j * 4] = v;
                }
            }
            __syncthreads();

            // GEMM: 4 k-steps of 8
            #pragma unroll
            for (int kk = 0; kk < 4; kk++) {
                const int c = kk * 8;
                uint32_t af[2][4];
                #pragma unroll
                for (int mt = 0; mt < 2; mt++) {
                    const int row = m0 + mt * 16 + g;
                    af[mt][0] = __float_as_uint(wn_s[(c + q) * SA + row]);
                    af[mt][1] = __float_as_uint(wn_s[(c + q) * SA + row + 8]);
                    af[mt][2] = __float_as_uint(wn_s[(c + q + 4) * SA + row]);
                    af[mt][3] = __float_as_uint(wn_s[(c + q + 4) * SA + row + 8]);
                }
                uint32_t bf[8][2];
                #pragma unroll
                for (int nt = 0; nt < 8; nt++) {
                    const int px = n0 + nt * 8 + g;
                    bf[nt][0] = __float_as_uint(cols_s[px * SB + c + q]);
                    bf[nt][1] = __float_as_uint(cols_s[px * SB + c + q + 4]);
                }
                #pragma unroll
                for (int mt = 0; mt < 2; mt++)
                    #pragma unroll
                    for (int nt = 0; nt < 8; nt++)
                        mma_tf32(acc[mt][nt], af[mt], bf[nt]);
            }
        }
    }

    // epilogue: out[b][cout][ho][wo]
    const int ho = ho0 + (n0 >> 6);
    #pragma unroll
    for (int mt = 0; mt < 2; mt++) {
        const int r0 = m0 + mt * 16 + g;
        #pragma unroll
        for (int nt = 0; nt < 8; nt++) {
            const int wo = (n0 + nt * 8 + 2 * q) & 63;
            float2 v0 = make_float2(acc[mt][nt][0], acc[mt][nt][1]);
            float2 v1 = make_float2(acc[mt][nt][2], acc[mt][nt][3]);
            *(float2*)&out[((size_t)(b * 128 + r0)     * HW) + ho * Wn + wo] = v0;
            *(float2*)&out[((size_t)(b * 128 + r0 + 8) * HW) + ho * Wn + wo] = v1;
        }
    }
}

// ---------------------------------------------------------------------------
extern "C" void kernel_launch(void* const* d_in, const int* in_sizes, int n_in,
                              void* d_out, int out_size) {
    const float* x      = (const float*)d_in[0];   // (8,128,64,64)
    const float* offset = (const float*)d_in[1];   // (8,18,64,64)
    const float* weight = (const float*)d_in[2];   // (128,128,3,3)
    float* out = (float*)d_out;                    // (8,128,64,64)

    transpose_kernel<<<4096, 256>>>(x);
    normw_kernel<<<KK, 128>>>(weight);
    deform_main_kernel<<<Bn * 32, 256>>>(offset, out);
}

// round 6
// speedup vs baseline: 1.7051x; 1.0170x over previous
#include <cuda_runtime.h>
#include <cstdint>

#define Bn 8
#define Hn 64
#define Wn 64
#define HW 4096
#define KK 9
#define EPSV 1e-4f
#define SA 136              // wn_s row stride (floats): (q*136+g)%32 = q*8+g unique
#define SB 36               // cols_s row stride (floats): (g*36+q)%32 = g*4+q unique

#define WN_FL   (32 * SA)                   // 4352 floats per wn stage
#define COL_FL  (256 * SB)                  // 9216 floats per cols stage
#define SMEM_FL (2 * (WN_FL + COL_FL))      // 27136 floats = 108544 B

__device__ float g_xt[Bn * HW * 128];       // x transposed [b][hw][c]
__device__ float g_wnt[KK * 128 * 128];     // normalized wn [k][c][o], tf32-rounded

__device__ __forceinline__ float to_tf32(float x) {
    float r; asm("cvt.rna.tf32.f32 %0, %1;" : "=f"(r) : "f"(x)); return r;
}
__device__ __forceinline__ uint32_t smem_u32(const void* p) {
    uint32_t a;
    asm("{ .reg .u64 t; cvta.to.shared.u64 t, %1; cvt.u32.u64 %0, t; }" : "=r"(a) : "l"(p));
    return a;
}
__device__ __forceinline__ void mma_tf32(float* d, const uint32_t* a, const uint32_t* b) {
    asm volatile(
        "mma.sync.aligned.m16n8k8.row.col.f32.tf32.tf32.f32 "
        "{%0,%1,%2,%3}, {%4,%5,%6,%7}, {%8,%9}, {%0,%1,%2,%3};"
        : "+f"(d[0]), "+f"(d[1]), "+f"(d[2]), "+f"(d[3])
        : "r"(a[0]), "r"(a[1]), "r"(a[2]), "r"(a[3]), "r"(b[0]), "r"(b[1]));
}
#define CP_ASYNC16(dst, src) \
    asm volatile("cp.async.ca.shared.global [%0], [%1], 16;" :: "r"(dst), "l"(src) : "memory")
#define CP_COMMIT()  asm volatile("cp.async.commit_group;" ::: "memory")
#define CP_WAIT0()   asm volatile("cp.async.wait_group 0;" ::: "memory")

// bilinear gather parameters for one (pixel, k)
struct GP {
    const float *p00, *p01, *p10, *p11;
    float w00, w01, w10, w11;
};
__device__ __forceinline__ GP gparams(const float* __restrict__ xb,
                                      const float* __restrict__ offset,
                                      int b, int k, int gho, int gwo) {
    const int ky = k / 3, kx = k - ky * 3;
    const float offy = __ldg(&offset[(((b * 18) + 2 * k    ) * Hn + gho) * Wn + gwo]);
    const float offx = __ldg(&offset[(((b * 18) + 2 * k + 1) * Hn + gho) * Wn + gwo]);
    const float py  = (float)(gho - 1 + ky) + offy;
    const float pxf = (float)(gwo - 1 + kx) + offx;
    const float y0f = floorf(py), x0f = floorf(pxf);
    const float ly = py - y0f, lx = pxf - x0f;
    const int y0 = (int)y0f, x0 = (int)x0f, y1 = y0 + 1, x1 = x0 + 1;
    GP g;
    g.w00 = (1.f - ly) * (1.f - lx); g.w01 = (1.f - ly) * lx;
    g.w10 = ly * (1.f - lx);         g.w11 = ly * lx;
    if (!((y0 >= 0) & (y0 < Hn) & (x0 >= 0) & (x0 < Wn))) g.w00 = 0.f;
    if (!((y0 >= 0) & (y0 < Hn) & (x1 >= 0) & (x1 < Wn))) g.w01 = 0.f;
    if (!((y1 >= 0) & (y1 < Hn) & (x0 >= 0) & (x0 < Wn))) g.w10 = 0.f;
    if (!((y1 >= 0) & (y1 < Hn) & (x1 >= 0) & (x1 < Wn))) g.w11 = 0.f;
    const int yc0 = min(max(y0, 0), Hn - 1), yc1 = min(max(y1, 0), Hn - 1);
    const int xc0 = min(max(x0, 0), Wn - 1), xc1 = min(max(x1, 0), Wn - 1);
    g.p00 = xb + (size_t)(yc0 * Wn + xc0) * 128;
    g.p01 = xb + (size_t)(yc0 * Wn + xc1) * 128;
    g.p10 = xb + (size_t)(yc1 * Wn + xc0) * 128;
    g.p11 = xb + (size_t)(yc1 * Wn + xc1) * 128;
    return g;
}

// ---- kernel 1: prep = transpose x + normalize weights (single launch) ----
__global__ void prep_kernel(const float* __restrict__ x, const float* __restrict__ w) {
    if (blockIdx.x < 4096) {
        __shared__ float s[32][33];
        int id = blockIdx.x;
        int b = id >> 9, rest = id & 511;
        int c0 = (rest >> 7) * 32, hw0 = (rest & 127) * 32;
        int tx = threadIdx.x & 31, ty = threadIdx.x >> 5;
        #pragma unroll
        for (int p = 0; p < 4; p++)
            s[ty + p * 8][tx] = x[(size_t)(b * 128 + c0 + ty + p * 8) * HW + hw0 + tx];
        __syncthreads();
        #pragma unroll
        for (int p = 0; p < 4; p++)
            g_xt[(size_t)(b * HW + hw0 + ty + p * 8) * 128 + c0 + tx] = s[tx][ty + p * 8];
    } else {
        int k = blockIdx.x - 4096;
        int o = threadIdx.x;
        if (o < 128) {
            float s = 0.f;
            #pragma unroll 8
            for (int c = 0; c < 128; c++) { float v = w[(o * 128 + c) * KK + k]; s += v * v; }
            float inv = 1.0f / (sqrtf(s + 128.0f * EPSV) * 3.0f);
            #pragma unroll 8
            for (int c = 0; c < 128; c++)
                g_wnt[(k * 128 + c) * 128 + o] = to_tf32(w[(o * 128 + c) * KK + k] * inv);
        }
    }
}

// ---- kernel 2: main — pipelined im2col gather + tf32 mma.sync GEMM ----
// grid 128, 512 thr. block = (b, 4 rows): D[128co][256px], 16 warps 32co x 64px
__global__ __launch_bounds__(512, 1)
void deform_main_kernel(const float* __restrict__ offset, float* __restrict__ out) {
    extern __shared__ float sm[];
    float* wnb[2]  = { sm, sm + WN_FL };
    float* colb[2] = { sm + 2 * WN_FL, sm + 2 * WN_FL + COL_FL };
    const uint32_t wnb_u32[2] = { smem_u32(wnb[0]), smem_u32(wnb[1]) };

    const int t = threadIdx.x;
    const int b = blockIdx.x >> 4;
    const int ho0 = (blockIdx.x & 15) * 4;

    // gather mapping: 2 threads per pixel, 16 channels each
    const int gpx = t >> 1, h = t & 1;
    const int gho = ho0 + (gpx >> 6), gwo = gpx & 63;
    // mma mapping: 16 warps = 4m x 4n
    const int w = t >> 5, lane = t & 31;
    const int m0 = (w & 3) * 32, n0 = (w >> 2) * 64;
    const int g = lane >> 2, q = lane & 3;

    float acc[2][8][4];
    #pragma unroll
    for (int mt = 0; mt < 2; mt++)
        #pragma unroll
        for (int nt = 0; nt < 8; nt++)
            #pragma unroll
            for (int r = 0; r < 4; r++) acc[mt][nt][r] = 0.f;

    const float* xb = g_xt + (size_t)b * HW * 128;

    // ---- prologue: gather chunk 0 into colb[0], cp.async wn chunk 0 ----
    GP gp = gparams(xb, offset, b, 0, gho, gwo);
    {
        #pragma unroll
        for (int sub = 0; sub < 4; sub++) {
            const int co = h * 16 + sub * 4;
            float4 a = *(const float4*)(gp.p00 + co);
            float4 bb = *(const float4*)(gp.p01 + co);
            float4 c = *(const float4*)(gp.p10 + co);
            float4 d = *(const float4*)(gp.p11 + co);
            float4 v;
            v.x = to_tf32(gp.w00 * a.x + gp.w01 * bb.x + gp.w10 * c.x + gp.w11 * d.x);
            v.y = to_tf32(gp.w00 * a.y + gp.w01 * bb.y + gp.w10 * c.y + gp.w11 * d.y);
            v.z = to_tf32(gp.w00 * a.z + gp.w01 * bb.z + gp.w10 * c.z + gp.w11 * d.z);
            v.w = to_tf32(gp.w00 * a.w + gp.w01 * bb.w + gp.w10 * c.w + gp.w11 * d.w);
            *(float4*)&colb[0][gpx * SB + co] = v;
        }
        const float* src = g_wnt;   // chunk 0
        #pragma unroll
        for (int p = 0; p < 2; p++) {
            int e16 = p * 512 + t;
            int c = e16 >> 5, off = (e16 & 31) * 4;
            CP_ASYNC16(wnb_u32[0] + (uint32_t)(c * SA + off) * 4, src + e16 * 4);
        }
        CP_COMMIT();
        CP_WAIT0();
    }

    // ---- pipelined main loop over 36 chunks ----
    for (int it = 0; it < 36; it++) {
        const int cur = it & 1, nxt = cur ^ 1;
        __syncthreads();     // colb[cur] STS visible; all warps done with [nxt] buffers

        const bool more = (it + 1 < 36);
        if (more) {
            // prefetch wn chunk it+1
            const float* src = g_wnt + (size_t)(it + 1) * 4096;
            #pragma unroll
            for (int p = 0; p < 2; p++) {
                int e16 = p * 512 + t;
                int c = e16 >> 5, off = (e16 & 31) * 4;
                CP_ASYNC16(wnb_u32[nxt] + (uint32_t)(c * SA + off) * 4, src + e16 * 4);
            }
            CP_COMMIT();
            if (((it + 1) & 3) == 0)
                gp = gparams(xb, offset, b, (it + 1) >> 2, gho, gwo);
        }
        const int ccn = (it + 1) & 3;           // c-chunk index of next
        const float* wnc = wnb[cur];
        const float* colc = colb[cur];
        float* coln = colb[nxt];

        #pragma unroll
        for (int sub = 0; sub < 4; sub++) {
            // issue next-chunk corner loads for this channel-quad (hidden under MMA)
            float4 a, bb, c, d;
            if (more) {
                const int co = ccn * 32 + h * 16 + sub * 4;   // global channel
                a  = *(const float4*)(gp.p00 + co);
                bb = *(const float4*)(gp.p01 + co);
                c  = *(const float4*)(gp.p10 + co);
                d  = *(const float4*)(gp.p11 + co);
            }
            // MMA k-step
            const int c8 = sub * 8;
            uint32_t af[2][4];
            #pragma unroll
            for (int mt = 0; mt < 2; mt++) {
                const int row = m0 + mt * 16 + g;
                af[mt][0] = __float_as_uint(wnc[(c8 + q) * SA + row]);
                af[mt][1] = __float_as_uint(wnc[(c8 + q) * SA + row + 8]);
                af[mt][2] = __float_as_uint(wnc[(c8 + q + 4) * SA + row]);
                af[mt][3] = __float_as_uint(wnc[(c8 + q + 4) * SA + row + 8]);
            }
            uint32_t bf[8][2];
            #pragma unroll
            for (int nt = 0; nt < 8; nt++) {
                const int px = n0 + nt * 8 + g;
                bf[nt][0] = __float_as_uint(colc[px * SB + c8 + q]);
                bf[nt][1] = __float_as_uint(colc[px * SB + c8 + q + 4]);
            }
            #pragma unroll
            for (int mt = 0; mt < 2; mt++)
                #pragma unroll
                for (int nt = 0; nt < 8; nt++)
                    mma_tf32(acc[mt][nt], af[mt], bf[nt]);

            // blend + store next-chunk quad (LOCAL channel index in smem!)
            if (more) {
                float4 v;
                v.x = to_tf32(gp.w00 * a.x + gp.w01 * bb.x + gp.w10 * c.x + gp.w11 * d.x);
                v.y = to_tf32(gp.w00 * a.y + gp.w01 * bb.y + gp.w10 * c.y + gp.w11 * d.y);
                v.z = to_tf32(gp.w00 * a.z + gp.w01 * bb.z + gp.w10 * c.z + gp.w11 * d.z);
                v.w = to_tf32(gp.w00 * a.w + gp.w01 * bb.w + gp.w10 * c.w + gp.w11 * d.w);
                *(float4*)&coln[gpx * SB + h * 16 + sub * 4] = v;
            }
        }
        if (more) CP_WAIT0();
    }

    // ---- epilogue: out[b][cout][ho][wo]; each warp owns one output row band ----
    const int ho = ho0 + (n0 >> 6);
    #pragma unroll
    for (int mt = 0; mt < 2; mt++) {
        const int r0 = m0 + mt * 16 + g;
        #pragma unroll
        for (int nt = 0; nt < 8; nt++) {
            const int wo = nt * 8 + 2 * q;
            float2 v0 = make_float2(acc[mt][nt][0], acc[mt][nt][1]);
            float2 v1 = make_float2(acc[mt][nt][2], acc[mt][nt][3]);
            *(float2*)&out[((size_t)(b * 128 + r0)     * HW) + ho * Wn + wo] = v0;
            *(float2*)&out[((size_t)(b * 128 + r0 + 8) * HW) + ho * Wn + wo] = v1;
        }
    }
}

// ---------------------------------------------------------------------------
extern "C" void kernel_launch(void* const* d_in, const int* in_sizes, int n_in,
                              void* d_out, int out_size) {
    const float* x      = (const float*)d_in[0];   // (8,128,64,64)
    const float* offset = (const float*)d_in[1];   // (8,18,64,64)
    const float* weight = (const float*)d_in[2];   // (128,128,3,3)
    float* out = (float*)d_out;                    // (8,128,64,64)

    cudaFuncSetAttribute(deform_main_kernel,
                         cudaFuncAttributeMaxDynamicSharedMemorySize, SMEM_FL * 4);
    prep_kernel<<<4105, 256>>>(x, weight);
    deform_main_kernel<<<128, 512, SMEM_FL * 4>>>(offset, out);
}